// round 10
// baseline (speedup 1.0000x reference)
#include <cuda_runtime.h>
#include <math.h>

#define NCLS 1000
#define NT 800
#define TSTEP 0.00125f
#define TOL 0.01f

__device__ __forceinline__ float ex2(float x) {
    float y;
    asm("ex2.approx.f32 %0, %1;" : "=f"(y) : "f"(x));
    return y;
}

__device__ __forceinline__ float warp_sum(float v) {
#pragma unroll
    for (int o = 16; o > 0; o >>= 1) v += __shfl_xor_sync(0xffffffffu, v, o);
    return v;
}

// One warp per row. No shared memory, no __syncthreads.
__global__ __launch_bounds__(32, 1)
void logit_compression_kernel(const float* __restrict__ logits,
                              float* __restrict__ out) {
    const int lane = threadIdx.x;       // 0..31
    const int row  = blockIdx.x;
    const float* lrow = logits + row * NCLS;
    float* orow = out + row * NCLS;

    // ---- load row, lane-major: r[k] = row[lane + 32k] (coalesced) ----
    float r[32];
#pragma unroll
    for (int k = 0; k < 32; k++) {
        int idx = lane + (k << 5);
        r[k] = (idx < NCLS) ? lrow[idx] : -INFINITY;
    }

    // ---- warp max (exact) ----
    float mv = r[0];
#pragma unroll
    for (int k = 1; k < 32; k++) mv = fmaxf(mv, r[k]);
#pragma unroll
    for (int o = 16; o > 0; o >>= 1) mv = fmaxf(mv, __shfl_xor_sync(0xffffffffu, mv, o));
    const float m = mv;

    // ---- d = fl(l - m); S1 with ACCURATE expf (decision-critical for conf) ----
    float d[32];
    float b0 = 0.0f, b1 = 0.0f, b2 = 0.0f, b3 = 0.0f;
#pragma unroll
    for (int k = 0; k < 32; k += 4) {
        d[k+0] = __fsub_rn(r[k+0], m);  b0 += expf(d[k+0]);
        d[k+1] = __fsub_rn(r[k+1], m);  b1 += expf(d[k+1]);
        d[k+2] = __fsub_rn(r[k+2], m);  b2 += expf(d[k+2]);
        d[k+3] = __fsub_rn(r[k+3], m);  b3 += expf(d[k+3]);
    }
    const float S1 = warp_sum((b0 + b1) + (b2 + b3));

    // ---- conf, bin, target confidence (reference rounding chain) ----
    const float conf = __fdiv_rn(1.0f, S1);
    int bi = (conf >= (2.0f / 3.0f)) ? 2 : (conf >= (1.0f / 3.0f)) ? 1 : 0;
    const float BL  = (bi == 0) ? 0.0f : (bi == 1) ? (1.0f / 3.0f) : (2.0f / 3.0f);
    const float NBL = (bi == 0) ? 0.8f : (bi == 1) ? 0.86666666666f : 0.93333333333f;
    const float nc  = __fadd_rn(NBL,
                     __fmul_rn((float)(1.0 / 15.0),
                               __fdiv_rn(__fsub_rn(conf, BL), 0.2666666667f)));

    // ---- binary search for first j with ct(j) >= nc - TOL ----
    // ct(j) = 1/S(u_j) is monotone non-decreasing in j (temps decrease, each
    // term ex2(d*c) shrinks, fixed summation tree preserves order).
    int lo = 0, hi = NT;          // hi == NT means "no true index found yet"
    float ct_hi = 0.0f;           // ct at index hi (valid when hi < NT)

    while (lo < hi) {             // exactly 10 iterations from [0,800)
        const int mid = (lo + hi) >> 1;
        const float t    = __fsub_rn(1.0f, __fmul_rn(TSTEP, (float)mid));
        const float invt = __frcp_rn(t);
        const float c2   = __fmul_rn(invt, 1.4426950408889634f);   // log2(e)/t
        float a0 = 0.0f, a1 = 0.0f, a2 = 0.0f, a3 = 0.0f;
#pragma unroll
        for (int k = 0; k < 32; k += 4) {
            a0 += ex2(__fmul_rn(d[k+0], c2));
            a1 += ex2(__fmul_rn(d[k+1], c2));
            a2 += ex2(__fmul_rn(d[k+2], c2));
            a3 += ex2(__fmul_rn(d[k+3], c2));
        }
        const float s  = warp_sum((a0 + a1) + (a2 + a3));
        const float ct = __frcp_rn(s);     // == 1/S, correctly rounded
        // all lanes hold identical s -> uniform branch
        if (__fsub_rn(ct, nc) >= -TOL) { hi = mid; ct_hi = ct; }
        else                           { lo = mid + 1; }
    }

    // ---- band check + output ----
    bool found = false;
    float tj = 1.0f;
    if (hi < NT) {
        float g = __fsub_rn(ct_hi, nc);    // >= -TOL by construction
        found = (fabsf(g) <= TOL);
        tj = __fsub_rn(1.0f, __fmul_rn(TSTEP, (float)hi));
    }
#pragma unroll
    for (int k = 0; k < 32; k++) {
        int idx = lane + (k << 5);
        if (idx < NCLS) orow[idx] = found ? __fdiv_rn(r[k], tj) : r[k];
    }
}

extern "C" void kernel_launch(void* const* d_in, const int* in_sizes, int n_in,
                              void* d_out, int out_size) {
    const float* logits = (const float*)d_in[0];
    float* out = (float*)d_out;
    int B = in_sizes[0] / NCLS;   // 128 rows
    logit_compression_kernel<<<B, 32>>>(logits, out);
}

// round 11
// speedup vs baseline: 1.1993x; 1.1993x over previous
#include <cuda_runtime.h>
#include <math.h>

#define NTHREADS 256
#define NW 8            // warps per block = probes per round
#define NCLS 1000
#define NT 800
#define TSTEP 0.00125f
#define TOL 0.01f
#define L2E 1.4426950408889634f

__device__ __forceinline__ float ex2(float x) {
    float y;
    asm("ex2.approx.f32 %0, %1;" : "=f"(y) : "f"(x));
    return y;
}

__global__ __launch_bounds__(NTHREADS)
void logit_compression_kernel(const float* __restrict__ logits,
                              float* __restrict__ out) {
    __shared__ float rsm[1024];          // raw logits, padded with -inf
    __shared__ float wmax[NW], wsum[NW];
    __shared__ float ctbuf[2][NW];

    const int tid  = threadIdx.x;
    const int lane = tid & 31;
    const int w    = tid >> 5;
    const int row  = blockIdx.x;
    const float* lrow = logits + row * NCLS;
    float* orow = out + row * NCLS;

    // ---- load row as float4 (1000 = 250 float4, rows 16B-aligned) ----
    float4 rv;
    if (tid < 250) rv = ((const float4*)lrow)[tid];
    else           rv = make_float4(-INFINITY, -INFINITY, -INFINITY, -INFINITY);
    ((float4*)rsm)[tid] = rv;            // publish raw row (padding = -inf)

    // ---- fused per-warp (max, sum) then single barrier ----
    float mw = fmaxf(fmaxf(rv.x, rv.y), fmaxf(rv.z, rv.w));
#pragma unroll
    for (int o = 16; o > 0; o >>= 1) mw = fmaxf(mw, __shfl_xor_sync(0xffffffffu, mw, o));
    // warp-local softmax sum relative to warp max (exp(-inf)==0 for padding)
    float sw = (__expf(rv.x - mw) + __expf(rv.y - mw))
             + (__expf(rv.z - mw) + __expf(rv.w - mw));
#pragma unroll
    for (int o = 16; o > 0; o >>= 1) sw += __shfl_xor_sync(0xffffffffu, sw, o);
    if (lane == 0) { wmax[w] = mw; wsum[w] = sw; }
    __syncthreads();                     // single setup barrier: publishes rsm too

    // all threads redundantly combine (fixed tree, deterministic)
    float m = fmaxf(fmaxf(fmaxf(wmax[0], wmax[1]), fmaxf(wmax[2], wmax[3])),
                    fmaxf(fmaxf(wmax[4], wmax[5]), fmaxf(wmax[6], wmax[7])));
    float t0 = wsum[0] * __expf(wmax[0] - m), t1 = wsum[1] * __expf(wmax[1] - m);
    float t2 = wsum[2] * __expf(wmax[2] - m), t3 = wsum[3] * __expf(wmax[3] - m);
    float t4 = wsum[4] * __expf(wmax[4] - m), t5 = wsum[5] * __expf(wmax[5] - m);
    float t6 = wsum[6] * __expf(wmax[6] - m), t7 = wsum[7] * __expf(wmax[7] - m);
    const float S1 = ((t0 + t1) + (t2 + t3)) + ((t4 + t5) + (t6 + t7));

    // ---- conf, bin, target confidence ----
    const float conf = __fdiv_rn(1.0f, S1);
    int bi = (conf >= (2.0f / 3.0f)) ? 2 : (conf >= (1.0f / 3.0f)) ? 1 : 0;
    const float BL  = (bi == 0) ? 0.0f : (bi == 1) ? (1.0f / 3.0f) : (2.0f / 3.0f);
    const float NBL = (bi == 0) ? 0.8f : (bi == 1) ? 0.86666666666f : 0.93333333333f;
    const float nc  = __fadd_rn(NBL,
                     __fmul_rn((float)(1.0 / 15.0),
                               __fdiv_rn(__fsub_rn(conf, BL), 0.2666666667f)));

    // ---- search for first j with ct(j) >= nc - TOL, ct = 1/S(u_j) ----
    // ct(j) monotone non-decreasing in j (temps decrease, each term shrinks,
    // fixed summation tree preserves order). Round 0: structural table
    // (nc >= 0.8 always => late crossings); fallback: uniform stride.
    const float4* r4 = (const float4*)rsm;
    const int P0[NW] = {480, 600, 672, 720, 752, 776, 792, 799};  // ascending

    int lo = 0, hi = NT;
    float ct_hi = 0.0f;
    int par = 0;
    bool tab = true;

    while (lo < hi) {
        const int stride = (hi - lo + NW - 1) >> 3;
        int pos; bool active;
        if (tab) { pos = P0[w];           active = true; }
        else     { pos = lo + w * stride; active = (pos < hi); }

        float ctv = 0.0f;
        if (active) {                                 // warp-uniform branch
            float t    = __fsub_rn(1.0f, __fmul_rn(TSTEP, (float)pos));
            float invt = __frcp_rn(t);
            float c2   = __fmul_rn(invt, L2E);        // log2(e)/t
            float mc2  = -m * c2;                     // term = ex2(r*c2 - m*c2)
            float a0 = 0.0f, a1 = 0.0f, a2 = 0.0f, a3 = 0.0f;
#pragma unroll
            for (int k = 0; k < 8; k++) {
                float4 v = r4[lane + k * 32];
                a0 += ex2(fmaf(v.x, c2, mc2));
                a1 += ex2(fmaf(v.y, c2, mc2));
                a2 += ex2(fmaf(v.z, c2, mc2));
                a3 += ex2(fmaf(v.w, c2, mc2));
            }
            float s = (a0 + a1) + (a2 + a3);
#pragma unroll
            for (int o = 16; o > 0; o >>= 1) s += __shfl_xor_sync(0xffffffffu, s, o);
            ctv = __frcp_rn(s);                       // ct = 1/S
        }
        if (lane == 0) ctbuf[par][w] = ctv;
        __syncthreads();   // single barrier per round (double-buffered ctbuf)

        // Deterministic redundant interval update.
        int first = -1;
        int pprev = 0, pfirst = 0, plast = 0;
#pragma unroll
        for (int i = 0; i < NW; i++) {
            int p  = tab ? P0[i] : (lo + i * stride);
            bool a = tab ? true  : (p < hi);
            if (a) {
                if (first < 0) {
                    if (__fsub_rn(ctbuf[par][i], nc) >= -TOL) { first = i; pfirst = p; }
                    else pprev = p;
                }
                plast = p;
            }
        }
        if (first >= 0) {
            ct_hi = ctbuf[par][first];
            hi = pfirst;
            if (first > 0) lo = pprev + 1;
            // first == 0 on table round: crossing may be < P0[0]; lo unchanged
        } else {
            lo = plast + 1;
        }
        par ^= 1;
        tab = false;
    }

    // ---- band check + output (float4 stores) ----
    float sc = 1.0f;
    if (hi < NT) {
        float g = __fsub_rn(ct_hi, nc);               // >= -TOL by construction
        if (fabsf(g) <= TOL) {
            float tj = __fsub_rn(1.0f, __fmul_rn(TSTEP, (float)hi));
            sc = __frcp_rn(tj);                       // out = r * (1/tj)
        }
    }
    if (tid < 250) {
        float4 o;
        o.x = rv.x * sc; o.y = rv.y * sc; o.z = rv.z * sc; o.w = rv.w * sc;
        ((float4*)orow)[tid] = o;
    }
}

extern "C" void kernel_launch(void* const* d_in, const int* in_sizes, int n_in,
                              void* d_out, int out_size) {
    const float* logits = (const float*)d_in[0];
    float* out = (float*)d_out;
    int B = in_sizes[0] / NCLS;   // 128 rows
    logit_compression_kernel<<<B, NTHREADS>>>(logits, out);
}